// round 3
// baseline (speedup 1.0000x reference)
#include <cuda_runtime.h>
#include <math.h>

// Problem constants
#define NB   4
#define C    256
#define H    64
#define W    64
#define HW   4096
#define NPIX 16384
#define G    8
#define GC   32
#define P    9
#define NOFF 144
#define NMSK 72

// GEMM tiling
#define BM 128
#define BN 128
#define BK 32
#define PK  132   // pitch for k-major tiles  (bank = 4*tig + gid)
#define PM  36    // pitch for m-major A tile (bank = 4*gid + tig)

#define A_KMAJ_FLOATS (BK * PK)     // 4224
#define A_MMAJ_FLOATS (BM * PM)     // 4608
#define B_FLOATS      (BK * PK)     // 4224
#define SMEM_KMAJ_BYTES ((2 * A_KMAJ_FLOATS + 2 * B_FLOATS) * 4)  // 67584
#define SMEM_MMAJ_BYTES ((2 * A_MMAJ_FLOATS + 2 * B_FLOATS) * 4)  // 70656

// -------- scratch --------
__device__ float g_xnhwc[NPIX * C];
__device__ float g_xproj[NPIX * C];
__device__ float g_x1   [NPIX * C];
__device__ float g_off  [NPIX * NOFF];
__device__ float g_mlog [NPIX * NMSK];
__device__ float g_agg  [NPIX * C];

__device__ __forceinline__ unsigned f2tf(float f) {
    unsigned r; asm("cvt.rna.tf32.f32 %0, %1;" : "=r"(r) : "f"(f)); return r;
}
__device__ __forceinline__ void cp16(float* dst_smem, const float* src, int nbytes) {
    unsigned d = (unsigned)__cvta_generic_to_shared(dst_smem);
    asm volatile("cp.async.cg.shared.global [%0], [%1], 16, %2;"
                 :: "r"(d), "l"(src), "r"(nbytes));
}
__device__ __forceinline__ void cp_commit() { asm volatile("cp.async.commit_group;"); }
template<int N> __device__ __forceinline__ void cp_wait() {
    asm volatile("cp.async.wait_group %0;" :: "n"(N));
}

// ============================================================
// NCHW -> NHWC transpose (needed by dwln branch only)
// ============================================================
extern "C" __global__ void __launch_bounds__(256)
transpose_kernel(const float* __restrict__ x)
{
    __shared__ float tile[32][33];
    const int n   = blockIdx.z;
    const int hw0 = blockIdx.x * 32;
    const int c0  = blockIdx.y * 32;
    const float* src = x + (size_t)n * C * HW;
    float*       dst = g_xnhwc + (size_t)n * HW * C;
    #pragma unroll
    for (int i = 0; i < 4; i++) {
        int cl = threadIdx.y + i * 8;
        tile[cl][threadIdx.x] = src[(size_t)(c0 + cl) * HW + hw0 + threadIdx.x];
    }
    __syncthreads();
    #pragma unroll
    for (int i = 0; i < 4; i++) {
        int hl = threadIdx.y + i * 8;
        dst[(size_t)(hw0 + hl) * C + c0 + threadIdx.x] = tile[threadIdx.x][hl];
    }
}

// ============================================================
// cp.async double-buffered tf32 GEMM pipeline.
// LAYOUT 0: A loaded k-major from NCHW x  (Asrc = x + n*C*HW + hw0; row k -> +k*HW)
// LAYOUT 1: A loaded m-major from row-major [M x 256] (Asrc = A + bm*256)
// MODE   0: dense B0[256 x 256]
// MODE   1: B = concat(B0[256 x 144], B1[256 x 72]), zero-fill beyond 216
// ============================================================
template<int LAYOUT, int MODE>
__device__ __forceinline__ void gemm_pipeline(
    const float* __restrict__ Asrc,
    const float* __restrict__ B0, const float* __restrict__ B1,
    int bn, float acc[4][4][4], float* smem)
{
    constexpr int ASTG = (LAYOUT == 0) ? A_KMAJ_FLOATS : A_MMAJ_FLOATS;
    float* As[2] = { smem, smem + ASTG };
    float* Bs[2] = { smem + 2 * ASTG, smem + 2 * ASTG + B_FLOATS };

    const int tid  = threadIdx.x;
    const int warp = tid >> 5, lane = tid & 31;
    const int gid  = lane >> 2, tig = lane & 3;
    const int wm   = warp >> 2, wn = warp & 3;

    auto load_stage = [&](int slab, int buf) {
        const int k0 = slab * BK;
        // ---- A ----
        #pragma unroll
        for (int i = 0; i < 4; i++) {
            int idx = tid + 256 * i;
            if (LAYOUT == 0) {
                int kr = idx >> 5, col = idx & 31;             // 32 rows x 32 chunks
                cp16(&As[buf][kr * PK + col * 4],
                     &Asrc[(size_t)(k0 + kr) * HW + col * 4], 16);
            } else {
                int mr = idx >> 3, col = idx & 7;              // 128 rows x 8 chunks
                cp16(&As[buf][mr * PM + col * 4],
                     &Asrc[(size_t)mr * 256 + k0 + col * 4], 16);
            }
        }
        // ---- B ----
        #pragma unroll
        for (int i = 0; i < 4; i++) {
            int idx = tid + 256 * i;
            int kr = idx >> 5, col = idx & 31;
            float* dst = &Bs[buf][kr * PK + col * 4];
            if (MODE == 0) {
                cp16(dst, &B0[(size_t)(k0 + kr) * 256 + bn + col * 4], 16);
            } else {
                int c = bn + col * 4;
                if (c < NOFF)
                    cp16(dst, &B0[(size_t)(k0 + kr) * NOFF + c], 16);
                else if (c < NOFF + NMSK)
                    cp16(dst, &B1[(size_t)(k0 + kr) * NMSK + (c - NOFF)], 16);
                else
                    cp16(dst, B0, 0);   // zero-fill
            }
        }
        cp_commit();
    };

    load_stage(0, 0);

    #pragma unroll 1
    for (int s = 0; s < 8; s++) {
        if (s + 1 < 8) load_stage(s + 1, (s + 1) & 1);
        if (s + 1 < 8) cp_wait<1>(); else cp_wait<0>();
        __syncthreads();

        const float* as = As[s & 1];
        const float* bs = Bs[s & 1];
        #pragma unroll
        for (int ks = 0; ks < 4; ks++) {
            unsigned a[4][4], b[4][2];
            #pragma unroll
            for (int mf = 0; mf < 4; mf++) {
                int m0 = wm * 64 + mf * 16;
                if (LAYOUT == 0) {
                    a[mf][0] = f2tf(as[(ks * 8 + tig    ) * PK + m0 + gid    ]);
                    a[mf][1] = f2tf(as[(ks * 8 + tig    ) * PK + m0 + gid + 8]);
                    a[mf][2] = f2tf(as[(ks * 8 + tig + 4) * PK + m0 + gid    ]);
                    a[mf][3] = f2tf(as[(ks * 8 + tig + 4) * PK + m0 + gid + 8]);
                } else {
                    a[mf][0] = f2tf(as[(m0 + gid    ) * PM + ks * 8 + tig    ]);
                    a[mf][1] = f2tf(as[(m0 + gid + 8) * PM + ks * 8 + tig    ]);
                    a[mf][2] = f2tf(as[(m0 + gid    ) * PM + ks * 8 + tig + 4]);
                    a[mf][3] = f2tf(as[(m0 + gid + 8) * PM + ks * 8 + tig + 4]);
                }
            }
            #pragma unroll
            for (int nf = 0; nf < 4; nf++) {
                int n0 = wn * 32 + nf * 8;
                b[nf][0] = f2tf(bs[(ks * 8 + tig    ) * PK + n0 + gid]);
                b[nf][1] = f2tf(bs[(ks * 8 + tig + 4) * PK + n0 + gid]);
            }
            #pragma unroll
            for (int mf = 0; mf < 4; mf++)
                #pragma unroll
                for (int nf = 0; nf < 4; nf++)
                    asm volatile(
                        "mma.sync.aligned.m16n8k8.row.col.f32.tf32.tf32.f32 "
                        "{%0,%1,%2,%3},{%4,%5,%6,%7},{%8,%9},{%0,%1,%2,%3};"
                        : "+f"(acc[mf][nf][0]), "+f"(acc[mf][nf][1]),
                          "+f"(acc[mf][nf][2]), "+f"(acc[mf][nf][3])
                        : "r"(a[mf][0]), "r"(a[mf][1]), "r"(a[mf][2]), "r"(a[mf][3]),
                          "r"(b[nf][0]), "r"(b[nf][1]));
        }
        __syncthreads();
    }
}

// ---- input projection: x(NCHW) @ w_in + b_in -> g_xproj (NHWC) ----
extern "C" __global__ void __launch_bounds__(256)
gemm_in_kernel(const float* __restrict__ x,
               const float* __restrict__ Bw, const float* __restrict__ bias)
{
    extern __shared__ float dsm[];
    float acc[4][4][4] = {};
    const int bm = blockIdx.y * BM, bn = blockIdx.x * BN;
    const int n = bm >> 12, hw0 = bm & 4095;
    gemm_pipeline<0, 0>(x + (size_t)n * C * HW + hw0, Bw, nullptr, bn, acc, dsm);

    const int lane = threadIdx.x & 31, warp = threadIdx.x >> 5;
    const int gid = lane >> 2, tig = lane & 3, wm = warp >> 2, wn = warp & 3;
    #pragma unroll
    for (int mf = 0; mf < 4; mf++) {
        int r0 = bm + wm * 64 + mf * 16 + gid;
        #pragma unroll
        for (int nf = 0; nf < 4; nf++) {
            int col = bn + wn * 32 + nf * 8 + 2 * tig;
            float bx = bias[col], by = bias[col + 1];
            float2 lo = {acc[mf][nf][0] + bx, acc[mf][nf][1] + by};
            float2 hi = {acc[mf][nf][2] + bx, acc[mf][nf][3] + by};
            *reinterpret_cast<float2*>(&g_xproj[(size_t)r0 * 256 + col])       = lo;
            *reinterpret_cast<float2*>(&g_xproj[(size_t)(r0 + 8) * 256 + col]) = hi;
        }
    }
}

// ---- fused offset+mask projection ----
extern "C" __global__ void __launch_bounds__(256)
gemm_offmask_kernel(const float* __restrict__ Bo, const float* __restrict__ Bm,
                    const float* __restrict__ bo, const float* __restrict__ bmk)
{
    extern __shared__ float dsm[];
    float acc[4][4][4] = {};
    const int bm = blockIdx.y * BM, bn = blockIdx.x * BN;
    gemm_pipeline<1, 1>(g_x1 + (size_t)bm * 256, Bo, Bm, bn, acc, dsm);

    const int lane = threadIdx.x & 31, warp = threadIdx.x >> 5;
    const int gid = lane >> 2, tig = lane & 3, wm = warp >> 2, wn = warp & 3;
    #pragma unroll
    for (int mf = 0; mf < 4; mf++) {
        int r0 = bm + wm * 64 + mf * 16 + gid;
        #pragma unroll
        for (int nf = 0; nf < 4; nf++) {
            int col = bn + wn * 32 + nf * 8 + 2 * tig;
            if (col >= NOFF + NMSK) continue;
            float bx, by; float *d0, *d1;
            if (col < NOFF) {
                bx = bo[col]; by = bo[col + 1];
                d0 = &g_off[(size_t)r0 * NOFF + col];
                d1 = &g_off[(size_t)(r0 + 8) * NOFF + col];
            } else {
                int mc = col - NOFF;
                bx = bmk[mc]; by = bmk[mc + 1];
                d0 = &g_mlog[(size_t)r0 * NMSK + mc];
                d1 = &g_mlog[(size_t)(r0 + 8) * NMSK + mc];
            }
            float2 lo = {acc[mf][nf][0] + bx, acc[mf][nf][1] + by};
            float2 hi = {acc[mf][nf][2] + bx, acc[mf][nf][3] + by};
            *reinterpret_cast<float2*>(d0) = lo;
            *reinterpret_cast<float2*>(d1) = hi;
        }
    }
}

// ---- output projection + bias + BN + SiLU -> NCHW ----
extern "C" __global__ void __launch_bounds__(256)
gemm_out_kernel(const float* __restrict__ Bw, const float* __restrict__ bias,
                const float* __restrict__ bn_g, const float* __restrict__ bn_b,
                const float* __restrict__ bn_mean, const float* __restrict__ bn_var,
                float* __restrict__ out)
{
    extern __shared__ float dsm[];
    float acc[4][4][4] = {};
    const int bm = blockIdx.y * BM, bn = blockIdx.x * BN;
    gemm_pipeline<1, 0>(g_agg + (size_t)bm * 256, Bw, nullptr, bn, acc, dsm);

    const int lane = threadIdx.x & 31, warp = threadIdx.x >> 5;
    const int gid = lane >> 2, tig = lane & 3, wm = warp >> 2, wn = warp & 3;
    #pragma unroll
    for (int nf = 0; nf < 4; nf++) {
        int colb = bn + wn * 32 + nf * 8 + 2 * tig;
        #pragma unroll
        for (int j = 0; j < 2; j++) {
            int col = colb + j;
            float sc = bn_g[col] * rsqrtf(bn_var[col] + 1e-5f);
            float sh = bn_b[col] - bn_mean[col] * sc;
            float bo = bias[col];
            #pragma unroll
            for (int mf = 0; mf < 4; mf++) {
                #pragma unroll
                for (int h2 = 0; h2 < 2; h2++) {
                    int row = bm + wm * 64 + mf * 16 + gid + 8 * h2;
                    float v = acc[mf][nf][2 * h2 + j] + bo;
                    v = v * sc + sh;
                    v = v / (1.f + expf(-v));
                    int n = row >> 12, hw = row & 4095;
                    out[((size_t)n * C + col) * HW + hw] = v;
                }
            }
        }
    }
}

// ============================================================
// Depthwise 3x3 + LayerNorm + exact GELU
// ============================================================
extern "C" __global__ void __launch_bounds__(256)
dwln_kernel(const float* __restrict__ w_dw, const float* __restrict__ b_dw,
            const float* __restrict__ ln_g, const float* __restrict__ ln_b)
{
    const int pix = blockIdx.x;
    const int c   = threadIdx.x;
    const int n = pix >> 12, hw = pix & 4095, h = hw >> 6, w = hw & 63;

    float wk[9];
    #pragma unroll
    for (int i = 0; i < 9; i++) wk[i] = w_dw[c * 9 + i];

    float acc = b_dw[c];
    #pragma unroll
    for (int ky = 0; ky < 3; ky++) {
        int yy = h + ky - 1;
        if (yy < 0 || yy > 63) continue;
        #pragma unroll
        for (int kx = 0; kx < 3; kx++) {
            int xx = w + kx - 1;
            if (xx < 0 || xx > 63) continue;
            acc += g_xnhwc[(((size_t)n * 64 + yy) * 64 + xx) * C + c] * wk[ky * 3 + kx];
        }
    }

    __shared__ float red[8];
    float s = acc;
    #pragma unroll
    for (int o = 16; o; o >>= 1) s += __shfl_xor_sync(0xffffffffu, s, o);
    if ((c & 31) == 0) red[c >> 5] = s;
    __syncthreads();
    float tot = 0.f;
    #pragma unroll
    for (int i = 0; i < 8; i++) tot += red[i];
    const float mean = tot * (1.f / 256.f);
    __syncthreads();
    float d  = acc - mean;
    float s2 = d * d;
    #pragma unroll
    for (int o = 16; o; o >>= 1) s2 += __shfl_xor_sync(0xffffffffu, s2, o);
    if ((c & 31) == 0) red[c >> 5] = s2;
    __syncthreads();
    float tot2 = 0.f;
    #pragma unroll
    for (int i = 0; i < 8; i++) tot2 += red[i];
    const float var = tot2 * (1.f / 256.f);

    float v = d * rsqrtf(var + 1e-5f) * ln_g[c] + ln_b[c];
    float ge = 0.5f * v * (1.f + erff(v * 0.70710678118654752f));
    g_x1[(size_t)pix * C + c] = ge;
}

// ============================================================
// Deformable sampling + softmax aggregation
// ============================================================
extern "C" __global__ void __launch_bounds__(256)
sample_kernel()
{
    const int pix = blockIdx.x;
    const int t   = threadIdx.x;
    const int g   = t >> 5, cc = t & 31;
    const int n = pix >> 12, hw = pix & 4095, h = hw >> 6, w = hw & 63;

    const float* ob = g_off  + (size_t)pix * NOFF + g * 18;
    const float* lb = g_mlog + (size_t)pix * NMSK + g * 9;

    float l[9], m = -1e30f;
    #pragma unroll
    for (int p = 0; p < 9; p++) { l[p] = lb[p]; m = fmaxf(m, l[p]); }
    float se = 0.f;
    #pragma unroll
    for (int p = 0; p < 9; p++) { l[p] = expf(l[p] - m); se += l[p]; }
    const float inv = 1.f / se;

    const float* base = g_xproj + (size_t)n * HW * C + g * GC + cc;
    float acc = 0.f;
    #pragma unroll
    for (int p = 0; p < 9; p++) {
        float gx = (float)(w + (p / 3)) + ob[2 * p + 0];
        float gy = (float)(h + (p % 3)) + ob[2 * p + 1];
        float x0f = floorf(gx), y0f = floorf(gy);
        int   x0 = (int)x0f, y0 = (int)y0f;
        float wx = gx - x0f, wy = gy - y0f;
        float w00 = (1.f - wx) * (1.f - wy);
        float w10 = wx * (1.f - wy);
        float w01 = (1.f - wx) * wy;
        float w11 = wx * wy;
        bool yi0 = (y0     >= 1 && y0     <= 64);
        bool yi1 = (y0 + 1 >= 1 && y0 + 1 <= 64);
        bool xi0 = (x0     >= 1 && x0     <= 64);
        bool xi1 = (x0 + 1 >= 1 && x0 + 1 <= 64);
        float v00 = 0.f, v10 = 0.f, v01 = 0.f, v11 = 0.f;
        if (yi0 && xi0) v00 = base[((size_t)(y0 - 1) * 64 + (x0 - 1)) * C];
        if (yi0 && xi1) v10 = base[((size_t)(y0 - 1) * 64 + (x0    )) * C];
        if (yi1 && xi0) v01 = base[((size_t)(y0    ) * 64 + (x0 - 1)) * C];
        if (yi1 && xi1) v11 = base[((size_t)(y0    ) * 64 + (x0    )) * C];
        acc += (l[p] * inv) * (w00 * v00 + w10 * v10 + w01 * v01 + w11 * v11);
    }
    g_agg[(size_t)pix * C + t] = acc;
}

// ============================================================
// launch
// ============================================================
extern "C" void kernel_launch(void* const* d_in, const int* in_sizes, int n_in,
                              void* d_out, int out_size)
{
    const float* x       = (const float*)d_in[0];
    const float* w_in    = (const float*)d_in[1];
    const float* b_in    = (const float*)d_in[2];
    const float* w_dw    = (const float*)d_in[3];
    const float* b_dw    = (const float*)d_in[4];
    const float* ln_g    = (const float*)d_in[5];
    const float* ln_b    = (const float*)d_in[6];
    const float* w_off   = (const float*)d_in[7];
    const float* b_off   = (const float*)d_in[8];
    const float* w_mask  = (const float*)d_in[9];
    const float* b_mask  = (const float*)d_in[10];
    const float* w_out   = (const float*)d_in[11];
    const float* b_out   = (const float*)d_in[12];
    const float* bn_g    = (const float*)d_in[13];
    const float* bn_b    = (const float*)d_in[14];
    const float* bn_mean = (const float*)d_in[15];
    const float* bn_var  = (const float*)d_in[16];
    float* out = (float*)d_out;

    cudaFuncSetAttribute(gemm_in_kernel,
        cudaFuncAttributeMaxDynamicSharedMemorySize, SMEM_MMAJ_BYTES);
    cudaFuncSetAttribute(gemm_offmask_kernel,
        cudaFuncAttributeMaxDynamicSharedMemorySize, SMEM_MMAJ_BYTES);
    cudaFuncSetAttribute(gemm_out_kernel,
        cudaFuncAttributeMaxDynamicSharedMemorySize, SMEM_MMAJ_BYTES);

    transpose_kernel   <<<dim3(HW / 32, C / 32, NB), dim3(32, 8)>>>(x);
    gemm_in_kernel     <<<dim3(C / BN, NPIX / BM), 256, SMEM_KMAJ_BYTES>>>(x, w_in, b_in);
    dwln_kernel        <<<NPIX, 256>>>(w_dw, b_dw, ln_g, ln_b);
    gemm_offmask_kernel<<<dim3(2, NPIX / BM), 256, SMEM_MMAJ_BYTES>>>(w_off, w_mask, b_off, b_mask);
    sample_kernel      <<<NPIX, 256>>>();
    gemm_out_kernel    <<<dim3(C / BN, NPIX / BM), 256, SMEM_MMAJ_BYTES>>>(w_out, b_out, bn_g, bn_b,
                                                                           bn_mean, bn_var, out);
}

// round 6
// speedup vs baseline: 1.1262x; 1.1262x over previous
#include <cuda_runtime.h>
#include <math.h>

// Problem constants
#define NB   4
#define C    256
#define H    64
#define W    64
#define HW   4096
#define NPIX 16384
#define G    8
#define GC   32
#define P    9
#define NOFF 144
#define NMSK 72

// GEMM tiling (round-2 core)
#define BM 128
#define BN 128
#define BK 32
#define PADT 136

// -------- scratch --------
__device__ float g_dw   [NPIX * C];   // depthwise conv output (NCHW)
__device__ float g_xproj[NPIX * C];   // input projection (NHWC)
__device__ float g_x1   [NPIX * C];   // LN+GELU branch (NHWC)
__device__ float g_off  [NPIX * NOFF];
__device__ float g_mlog [NPIX * NMSK];
__device__ float g_agg  [NPIX * C];   // sampled+aggregated (NHWC)

__device__ __forceinline__ unsigned f2tf(float f) {
    unsigned r; asm("cvt.rna.tf32.f32 %0, %1;" : "=r"(r) : "f"(f)); return r;
}

// ============================================================
// tf32 mma.sync GEMM core (register prefetch, convert at stage).
// LAYOUT 0: A k-major source, PRE-OFFSET: element (k,m) at Asrc[k*HW + m]
// LAYOUT 1: A m-major source, PRE-OFFSET: element (m,k) at Asrc[m*256 + k]
// MODE   0: dense B0[256 x 256]
// MODE   1: B = concat(B0[256x144], B1[256x72]); cols >= 216 zero
// ============================================================
template<int LAYOUT, int MODE>
__device__ __forceinline__ void gemm_core(
    const float* __restrict__ Asrc,
    const float* __restrict__ B0, const float* __restrict__ B1,
    int bn, float acc[4][4][4])
{
    __shared__ float As[BK][PADT];
    __shared__ float Bs[BK][PADT];
    const int tid  = threadIdx.x;
    const int warp = tid >> 5, lane = tid & 31;
    const int gid  = lane >> 2, tig = lane & 3;
    const int wm   = warp >> 2, wn = warp & 3;

    float4 aReg[4], bReg[4];

    auto loadAB = [&](int k0) {
        #pragma unroll
        for (int i = 0; i < 4; i++) {
            if (LAYOUT == 0) {
                int idx = tid + 256 * i;
                int kr = idx >> 5, col = idx & 31;   // 32 k-rows x 32 float4
                aReg[i] = *reinterpret_cast<const float4*>(
                    &Asrc[(size_t)(k0 + kr) * HW + col * 4]);
            } else {
                aReg[i] = *reinterpret_cast<const float4*>(
                    &Asrc[(size_t)(lane + 32 * i) * 256 + k0 + warp * 4]);
            }
        }
        #pragma unroll
        for (int i = 0; i < 4; i++) {
            int k = k0 + warp + 8 * i;
            if (MODE == 0) {
                bReg[i] = *reinterpret_cast<const float4*>(&B0[(size_t)k * 256 + bn + lane * 4]);
            } else {
                int c = bn + lane * 4;
                if (c < NOFF)
                    bReg[i] = *reinterpret_cast<const float4*>(&B0[(size_t)k * NOFF + c]);
                else if (c < NOFF + NMSK)
                    bReg[i] = *reinterpret_cast<const float4*>(&B1[(size_t)k * NMSK + c - NOFF]);
                else
                    bReg[i] = make_float4(0.f, 0.f, 0.f, 0.f);
            }
        }
    };

    auto stage = [&]() {
        #pragma unroll
        for (int i = 0; i < 4; i++) {
            if (LAYOUT == 0) {
                int idx = tid + 256 * i;
                int kr = idx >> 5, col = idx & 31;
                float4 t;
                t.x = __uint_as_float(f2tf(aReg[i].x));
                t.y = __uint_as_float(f2tf(aReg[i].y));
                t.z = __uint_as_float(f2tf(aReg[i].z));
                t.w = __uint_as_float(f2tf(aReg[i].w));
                *reinterpret_cast<float4*>(&As[kr][col * 4]) = t;
            } else {
                int m = lane + 32 * i;
                As[warp * 4 + 0][m] = __uint_as_float(f2tf(aReg[i].x));
                As[warp * 4 + 1][m] = __uint_as_float(f2tf(aReg[i].y));
                As[warp * 4 + 2][m] = __uint_as_float(f2tf(aReg[i].z));
                As[warp * 4 + 3][m] = __uint_as_float(f2tf(aReg[i].w));
            }
            float4 bt;
            bt.x = __uint_as_float(f2tf(bReg[i].x));
            bt.y = __uint_as_float(f2tf(bReg[i].y));
            bt.z = __uint_as_float(f2tf(bReg[i].z));
            bt.w = __uint_as_float(f2tf(bReg[i].w));
            *reinterpret_cast<float4*>(&Bs[warp + 8 * i][lane * 4]) = bt;
        }
    };

    loadAB(0);
    for (int k0 = 0; k0 < 256; k0 += BK) {
        __syncthreads();
        stage();
        __syncthreads();
        if (k0 + BK < 256) loadAB(k0 + BK);
        #pragma unroll
        for (int ks = 0; ks < 4; ks++) {
            unsigned a[4][4], b[4][2];
            #pragma unroll
            for (int mf = 0; mf < 4; mf++) {
                int m0 = wm * 64 + mf * 16;
                a[mf][0] = __float_as_uint(As[ks * 8 + tig    ][m0 + gid    ]);
                a[mf][1] = __float_as_uint(As[ks * 8 + tig    ][m0 + gid + 8]);
                a[mf][2] = __float_as_uint(As[ks * 8 + tig + 4][m0 + gid    ]);
                a[mf][3] = __float_as_uint(As[ks * 8 + tig + 4][m0 + gid + 8]);
            }
            #pragma unroll
            for (int nf = 0; nf < 4; nf++) {
                int n0 = wn * 32 + nf * 8;
                b[nf][0] = __float_as_uint(Bs[ks * 8 + tig    ][n0 + gid]);
                b[nf][1] = __float_as_uint(Bs[ks * 8 + tig + 4][n0 + gid]);
            }
            #pragma unroll
            for (int mf = 0; mf < 4; mf++)
                #pragma unroll
                for (int nf = 0; nf < 4; nf++)
                    asm volatile(
                        "mma.sync.aligned.m16n8k8.row.col.f32.tf32.tf32.f32 "
                        "{%0,%1,%2,%3},{%4,%5,%6,%7},{%8,%9},{%0,%1,%2,%3};"
                        : "+f"(acc[mf][nf][0]), "+f"(acc[mf][nf][1]),
                          "+f"(acc[mf][nf][2]), "+f"(acc[mf][nf][3])
                        : "r"(a[mf][0]), "r"(a[mf][1]), "r"(a[mf][2]), "r"(a[mf][3]),
                          "r"(b[nf][0]), "r"(b[nf][1]));
        }
    }
}

// ---- input projection: x(NCHW) @ w_in + b_in -> g_xproj (NHWC) ----
extern "C" __global__ void __launch_bounds__(256)
gemm_in_kernel(const float* __restrict__ x,
               const float* __restrict__ Bw, const float* __restrict__ bias)
{
    float acc[4][4][4] = {};
    const int bm = blockIdx.y * BM, bn = blockIdx.x * BN;
    const int n = bm >> 12, hw0 = bm & 4095;
    gemm_core<0, 0>(x + (size_t)n * C * HW + hw0, Bw, nullptr, bn, acc);

    const int lane = threadIdx.x & 31, warp = threadIdx.x >> 5;
    const int gid = lane >> 2, tig = lane & 3, wm = warp >> 2, wn = warp & 3;
    #pragma unroll
    for (int mf = 0; mf < 4; mf++) {
        int r0 = bm + wm * 64 + mf * 16 + gid;
        #pragma unroll
        for (int nf = 0; nf < 4; nf++) {
            int col = bn + wn * 32 + nf * 8 + 2 * tig;
            float bx = bias[col], by = bias[col + 1];
            float2 lo = {acc[mf][nf][0] + bx, acc[mf][nf][1] + by};
            float2 hi = {acc[mf][nf][2] + bx, acc[mf][nf][3] + by};
            *reinterpret_cast<float2*>(&g_xproj[(size_t)r0 * 256 + col])       = lo;
            *reinterpret_cast<float2*>(&g_xproj[(size_t)(r0 + 8) * 256 + col]) = hi;
        }
    }
}

// ---- fused offset+mask projection ----
extern "C" __global__ void __launch_bounds__(256)
gemm_offmask_kernel(const float* __restrict__ Bo, const float* __restrict__ Bm,
                    const float* __restrict__ bo, const float* __restrict__ bmk)
{
    float acc[4][4][4] = {};
    const int bm = blockIdx.y * BM, bn = blockIdx.x * BN;
    gemm_core<1, 1>(g_x1 + (size_t)bm * 256, Bo, Bm, bn, acc);

    const int lane = threadIdx.x & 31, warp = threadIdx.x >> 5;
    const int gid = lane >> 2, tig = lane & 3, wm = warp >> 2, wn = warp & 3;
    #pragma unroll
    for (int mf = 0; mf < 4; mf++) {
        int r0 = bm + wm * 64 + mf * 16 + gid;
        #pragma unroll
        for (int nf = 0; nf < 4; nf++) {
            int col = bn + wn * 32 + nf * 8 + 2 * tig;
            if (col >= NOFF + NMSK) continue;
            float bx, by; float *d0, *d1;
            if (col < NOFF) {
                bx = bo[col]; by = bo[col + 1];
                d0 = &g_off[(size_t)r0 * NOFF + col];
                d1 = &g_off[(size_t)(r0 + 8) * NOFF + col];
            } else {
                int mc = col - NOFF;
                bx = bmk[mc]; by = bmk[mc + 1];
                d0 = &g_mlog[(size_t)r0 * NMSK + mc];
                d1 = &g_mlog[(size_t)(r0 + 8) * NMSK + mc];
            }
            float2 lo = {acc[mf][nf][0] + bx, acc[mf][nf][1] + by};
            float2 hi = {acc[mf][nf][2] + bx, acc[mf][nf][3] + by};
            *reinterpret_cast<float2*>(d0) = lo;
            *reinterpret_cast<float2*>(d1) = hi;
        }
    }
}

// ---- output projection + bias + BN + SiLU -> NCHW ----
extern "C" __global__ void __launch_bounds__(256)
gemm_out_kernel(const float* __restrict__ Bw, const float* __restrict__ bias,
                const float* __restrict__ bn_g, const float* __restrict__ bn_b,
                const float* __restrict__ bn_mean, const float* __restrict__ bn_var,
                float* __restrict__ out)
{
    float acc[4][4][4] = {};
    const int bm = blockIdx.y * BM, bn = blockIdx.x * BN;
    gemm_core<1, 0>(g_agg + (size_t)bm * 256, Bw, nullptr, bn, acc);

    const int lane = threadIdx.x & 31, warp = threadIdx.x >> 5;
    const int gid = lane >> 2, tig = lane & 3, wm = warp >> 2, wn = warp & 3;
    #pragma unroll
    for (int nf = 0; nf < 4; nf++) {
        int colb = bn + wn * 32 + nf * 8 + 2 * tig;
        #pragma unroll
        for (int j = 0; j < 2; j++) {
            int col = colb + j;
            float sc = bn_g[col] * rsqrtf(bn_var[col] + 1e-5f);
            float sh = bn_b[col] - bn_mean[col] * sc;
            float bo = bias[col];
            #pragma unroll
            for (int mf = 0; mf < 4; mf++) {
                #pragma unroll
                for (int h2 = 0; h2 < 2; h2++) {
                    int row = bm + wm * 64 + mf * 16 + gid + 8 * h2;
                    float v = acc[mf][nf][2 * h2 + j] + bo;
                    v = v * sc + sh;
                    v = v / (1.f + expf(-v));
                    int n = row >> 12, hw = row & 4095;
                    out[((size_t)n * C + col) * HW + hw] = v;
                }
            }
        }
    }
}

// ============================================================
// Depthwise 3x3 conv, NCHW-native. One block per (n,c) plane.
// ============================================================
extern "C" __global__ void __launch_bounds__(256)
dwconv_kernel(const float* __restrict__ x,
              const float* __restrict__ w_dw, const float* __restrict__ b_dw)
{
    __shared__ float sp[HW];   // 16 KB plane
    const int n = blockIdx.x >> 8, c = blockIdx.x & 255;
    const int tid = threadIdx.x;
    const float* src = x + ((size_t)n * C + c) * HW;

    #pragma unroll
    for (int i = 0; i < 4; i++)
        *reinterpret_cast<float4*>(&sp[(tid + 256 * i) * 4]) =
            *reinterpret_cast<const float4*>(&src[(tid + 256 * i) * 4]);

    float wk[9];
    #pragma unroll
    for (int i = 0; i < 9; i++) wk[i] = w_dw[c * 9 + i];
    const float bb = b_dw[c];
    __syncthreads();

    float* dst = g_dw + ((size_t)n * C + c) * HW;
    #pragma unroll
    for (int i = 0; i < 16; i++) {
        int hw = tid + 256 * i;
        int h = hw >> 6, w = hw & 63;
        float acc = bb;
        #pragma unroll
        for (int ky = 0; ky < 3; ky++) {
            int yy = h + ky - 1;
            if (yy < 0 || yy > 63) continue;
            #pragma unroll
            for (int kx = 0; kx < 3; kx++) {
                int xx = w + kx - 1;
                if (xx < 0 || xx > 63) continue;
                acc += sp[yy * 64 + xx] * wk[ky * 3 + kx];
            }
        }
        dst[hw] = acc;
    }
}

// ============================================================
// LayerNorm + exact GELU + NCHW->NHWC transpose.
// Block = 32 pixels x 256 channels; pitch-33 smem -> conflict-free.
// ============================================================
extern "C" __global__ void __launch_bounds__(256)
lnT_kernel(const float* __restrict__ ln_g, const float* __restrict__ ln_b)
{
    __shared__ float t[256][33];
    __shared__ float smean[32], sivar[32];
    const int n   = blockIdx.x >> 7;
    const int hw0 = (blockIdx.x & 127) * 32;
    const int tid = threadIdx.x;
    const int lane = tid & 31, wp = tid >> 5;

    const float* src = g_dw + (size_t)n * C * HW + hw0;
    #pragma unroll
    for (int r = 0; r < 32; r++) {
        int c = wp + 8 * r;
        t[c][lane] = src[(size_t)c * HW + lane];
    }
    __syncthreads();

    #pragma unroll
    for (int q = 0; q < 4; q++) {
        int p = wp * 4 + q;
        float s = 0.f;
        #pragma unroll
        for (int j = 0; j < 8; j++) s += t[lane + 32 * j][p];
        #pragma unroll
        for (int o = 16; o; o >>= 1) s += __shfl_xor_sync(0xffffffffu, s, o);
        float mu = s * (1.f / 256.f);
        float v = 0.f;
        #pragma unroll
        for (int j = 0; j < 8; j++) { float d = t[lane + 32 * j][p] - mu; v += d * d; }
        #pragma unroll
        for (int o = 16; o; o >>= 1) v += __shfl_xor_sync(0xffffffffu, v, o);
        if (lane == 0) { smean[p] = mu; sivar[p] = rsqrtf(v * (1.f / 256.f) + 1e-5f); }
    }
    __syncthreads();

    const float lg = ln_g[tid], lb = ln_b[tid];
    const size_t pixbase = (size_t)n * HW + hw0;
    #pragma unroll
    for (int p = 0; p < 32; p++) {
        float v = (t[tid][p] - smean[p]) * sivar[p] * lg + lb;
        float ge = 0.5f * v * (1.f + erff(v * 0.70710678118654752f));
        g_x1[(pixbase + p) * C + tid] = ge;
    }
}

// ============================================================
// Deformable sampling + softmax aggregation
// ============================================================
extern "C" __global__ void __launch_bounds__(256)
sample_kernel()
{
    const int pix = blockIdx.x;
    const int t   = threadIdx.x;
    const int g   = t >> 5, cc = t & 31;
    const int n = pix >> 12, hw = pix & 4095, h = hw >> 6, w = hw & 63;

    const float* ob = g_off  + (size_t)pix * NOFF + g * 18;
    const float* lb = g_mlog + (size_t)pix * NMSK + g * 9;

    float l[9], m = -1e30f;
    #pragma unroll
    for (int p = 0; p < 9; p++) { l[p] = lb[p]; m = fmaxf(m, l[p]); }
    float se = 0.f;
    #pragma unroll
    for (int p = 0; p < 9; p++) { l[p] = expf(l[p] - m); se += l[p]; }
    const float inv = 1.f / se;

    const float* base = g_xproj + (size_t)n * HW * C + g * GC + cc;
    float acc = 0.f;
    #pragma unroll
    for (int p = 0; p < 9; p++) {
        float gx = (float)(w + (p / 3)) + ob[2 * p + 0];
        float gy = (float)(h + (p % 3)) + ob[2 * p + 1];
        float x0f = floorf(gx), y0f = floorf(gy);
        int   x0 = (int)x0f, y0 = (int)y0f;
        float wx = gx - x0f, wy = gy - y0f;
        float w00 = (1.f - wx) * (1.f - wy);
        float w10 = wx * (1.f - wy);
        float w01 = (1.f - wx) * wy;
        float w11 = wx * wy;
        bool yi0 = (y0     >= 1 && y0     <= 64);
        bool yi1 = (y0 + 1 >= 1 && y0 + 1 <= 64);
        bool xi0 = (x0     >= 1 && x0     <= 64);
        bool xi1 = (x0 + 1 >= 1 && x0 + 1 <= 64);
        float v00 = 0.f, v10 = 0.f, v01 = 0.f, v11 = 0.f;
        if (yi0 && xi0) v00 = base[((size_t)(y0 - 1) * 64 + (x0 - 1)) * C];
        if (yi0 && xi1) v10 = base[((size_t)(y0 - 1) * 64 + (x0    )) * C];
        if (yi1 && xi0) v01 = base[((size_t)(y0    ) * 64 + (x0 - 1)) * C];
        if (yi1 && xi1) v11 = base[((size_t)(y0    ) * 64 + (x0    )) * C];
        acc += (l[p] * inv) * (w00 * v00 + w10 * v10 + w01 * v01 + w11 * v11);
    }
    g_agg[(size_t)pix * C + t] = acc;
}

// ============================================================
// launch (gemm_in forked onto a side stream)
// ============================================================
extern "C" void kernel_launch(void* const* d_in, const int* in_sizes, int n_in,
                              void* d_out, int out_size)
{
    const float* x       = (const float*)d_in[0];
    const float* w_in    = (const float*)d_in[1];
    const float* b_in    = (const float*)d_in[2];
    const float* w_dw    = (const float*)d_in[3];
    const float* b_dw    = (const float*)d_in[4];
    const float* ln_g    = (const float*)d_in[5];
    const float* ln_b    = (const float*)d_in[6];
    const float* w_off   = (const float*)d_in[7];
    const float* b_off   = (const float*)d_in[8];
    const float* w_mask  = (const float*)d_in[9];
    const float* b_mask  = (const float*)d_in[10];
    const float* w_out   = (const float*)d_in[11];
    const float* b_out   = (const float*)d_in[12];
    const float* bn_g    = (const float*)d_in[13];
    const float* bn_b    = (const float*)d_in[14];
    const float* bn_mean = (const float*)d_in[15];
    const float* bn_var  = (const float*)d_in[16];
    float* out = (float*)d_out;

    static cudaStream_t s2 = nullptr;
    static cudaEvent_t evA = nullptr, evB = nullptr;
    if (!s2) {
        cudaStreamCreateWithFlags(&s2, cudaStreamNonBlocking);
        cudaEventCreateWithFlags(&evA, cudaEventDisableTiming);
        cudaEventCreateWithFlags(&evB, cudaEventDisableTiming);
    }

    // fork: gemm_in depends only on x
    cudaEventRecord(evA, 0);
    cudaStreamWaitEvent(s2, evA, 0);
    gemm_in_kernel<<<dim3(C / BN, NPIX / BM), 256, 0, s2>>>(x, w_in, b_in);
    cudaEventRecord(evB, s2);

    // main chain: dwconv -> LN/GELU/transpose -> offset+mask GEMM
    dwconv_kernel      <<<NB * C, 256>>>(x, w_dw, b_dw);
    lnT_kernel         <<<NPIX / 32, 256>>>(ln_g, ln_b);
    gemm_offmask_kernel<<<dim3(2, NPIX / BM), 256>>>(w_off, w_mask, b_off, b_mask);

    // join, then sampling + output projection
    cudaStreamWaitEvent(0, evB, 0);
    sample_kernel  <<<NPIX, 256>>>();
    gemm_out_kernel<<<dim3(C / BN, NPIX / BM), 256>>>(w_out, b_out, bn_g, bn_b,
                                                      bn_mean, bn_var, out);
}